// round 8
// baseline (speedup 1.0000x reference)
#include <cuda_runtime.h>
#include <cstdint>

#define NN   2048
#define EE   262144
#define SD   256
#define VD   64
#define ED   32
#define NMOL 64
#define NAF  16
#define NBT  5
#define EPC  64            // edges per CTA in k_edge

// ---- scratch (device globals; no allocations) ----
__device__ __align__(16) float g_G[NN * SD];         // G = s_h @ W0[0:256,:] (fp32)
__device__ __align__(16) float g_cpraw[NN * 3];
__device__ __align__(16) float g_cp[NN * 3];
__device__ __align__(16) float g_molmean[NMOL * 3];
__device__ __align__(16) float g_M[ED * SD];         // M = Wb@W0a, tf32-rounded bits
__device__ __align__(16) float g_c0[SD];             // c0 = b0 + bb @ W0a (fp32)
__device__ int   g_map[NN * NN];

__device__ __forceinline__ float silu_f(float x) {
    return __fdividef(x, 1.0f + __expf(-x));
}

__device__ __forceinline__ uint32_t f2tf32(float x) {
    uint32_t r;
    asm("cvt.rna.tf32.f32 %0, %1;" : "=r"(r) : "f"(x));
    return r;
}

// m16n8k8 tf32 mma: D += A@B  (A row-major, B col-major)
__device__ __forceinline__ void mma_tf32(float* c, const uint32_t* a,
                                         uint32_t b0, uint32_t b1) {
    asm volatile(
        "mma.sync.aligned.m16n8k8.row.col.f32.tf32.tf32.f32 "
        "{%0,%1,%2,%3}, {%4,%5,%6,%7}, {%8,%9}, {%0,%1,%2,%3};\n"
        : "+f"(c[0]), "+f"(c[1]), "+f"(c[2]), "+f"(c[3])
        : "r"(a[0]), "r"(a[1]), "r"(a[2]), "r"(a[3]), "r"(b0), "r"(b1));
}

// ---- K0: clear map ----
__global__ void k_clear() {
    int i = blockIdx.x * blockDim.x + threadIdx.x;
    int stride = gridDim.x * blockDim.x;
    for (; i < NN * NN; i += stride) g_map[i] = -1;
}

// ---- K5: scatter last-edge-wins ----
__global__ void k_scatter(const int* __restrict__ eg) {
    int k = blockIdx.x * blockDim.x + threadIdx.x;
    if (k < EE) {
        int j = eg[k];
        int i = eg[EE + k];
        atomicMax(&g_map[j * NN + i], k);
    }
}

// ---- K1: fused node kernel, 16 nodes/CTA: s_h (smem) -> G, atoms, coords ----
__global__ __launch_bounds__(256) void k_node(
    const float* __restrict__ s, const float* __restrict__ v,
    const float* __restrict__ p, const float* __restrict__ Ws,
    const float* __restrict__ bs, const float* __restrict__ Wc,
    const float* __restrict__ W0, const float* __restrict__ Wa,
    const float* __restrict__ ba, float* __restrict__ out_atoms)
{
    __shared__ float ss[16][SD];
    __shared__ float sh[16][SD];
    const int t = threadIdx.x;
    const int n0 = blockIdx.x * 16;
    #pragma unroll
    for (int r = 0; r < 16; r++) ss[r][t] = s[(n0 + r) * SD + t];
    __syncthreads();

    float acc[16];
    #pragma unroll
    for (int r = 0; r < 16; r++) acc[r] = 0.0f;
    for (int k = 0; k < SD; k += 4) {
        float w0 = Ws[(k + 0) * SD + t];
        float w1 = Ws[(k + 1) * SD + t];
        float w2 = Ws[(k + 2) * SD + t];
        float w3 = Ws[(k + 3) * SD + t];
        #pragma unroll
        for (int r = 0; r < 16; r++) {
            float4 a = *(const float4*)&ss[r][k];
            acc[r] += a.x * w0;
            acc[r] += a.y * w1;
            acc[r] += a.z * w2;
            acc[r] += a.w * w3;
        }
    }
    float b = bs[t];
    #pragma unroll
    for (int r = 0; r < 16; r++) sh[r][t] = silu_f(acc[r] + b);

    if (t < 48) {   // 16 nodes x 3 axes
        int r = t / 3, x = t % 3;
        const float* vp = &v[(n0 + r) * 3 * VD + x * VD];
        float sum = 0.0f;
        #pragma unroll 8
        for (int q = 0; q < VD; q++) sum += vp[q] * Wc[q];
        g_cpraw[(n0 + r) * 3 + x] = p[(n0 + r) * 3 + x] + sum;
    }
    __syncthreads();

    #pragma unroll
    for (int r = 0; r < 16; r++) acc[r] = 0.0f;
    for (int k = 0; k < SD; k += 4) {
        float w0 = W0[(k + 0) * SD + t];
        float w1 = W0[(k + 1) * SD + t];
        float w2 = W0[(k + 2) * SD + t];
        float w3 = W0[(k + 3) * SD + t];
        #pragma unroll
        for (int r = 0; r < 16; r++) {
            float4 a = *(const float4*)&sh[r][k];
            acc[r] += a.x * w0;
            acc[r] += a.y * w1;
            acc[r] += a.z * w2;
            acc[r] += a.w * w3;
        }
    }
    #pragma unroll
    for (int r = 0; r < 16; r++) g_G[(n0 + r) * SD + t] = acc[r];

    {   // atoms: 256 threads = 16 nodes x 16 features
        int r = t >> 4, a = t & 15;
        float sum = 0.0f;
        for (int k = 0; k < SD; k++) sum += sh[r][k] * Wa[k * NAF + a];
        out_atoms[(n0 + r) * NAF + a] = sum + ba[a];
    }
}

// ---- K2: g_M[k][n] = (Wb@W0a)[k][n] tf32-rounded; c0 = b0 + bb@W0a ----
__global__ __launch_bounds__(1024) void k_mw(
    const float* __restrict__ Wb, const float* __restrict__ bb,
    const float* __restrict__ W0, const float* __restrict__ b0)
{
    __shared__ float row[SD];
    __shared__ float part[3][SD];
    const int t = threadIdx.x;
    const int c = t & 255;
    const int pz = t >> 8;
    const int q = blockIdx.x;
    if (t < SD) row[t] = (q < ED) ? Wb[q * SD + t] : bb[t];
    __syncthreads();

    float acc = 0.0f;
    const int k0 = pz * 64;
    #pragma unroll 4
    for (int k = k0; k < k0 + 64; k += 4) {
        float4 a = *(const float4*)&row[k];
        acc += a.x * W0[(k + 0) * SD + c];
        acc += a.y * W0[(k + 1) * SD + c];
        acc += a.z * W0[(k + 2) * SD + c];
        acc += a.w * W0[(k + 3) * SD + c];
    }
    if (pz > 0) part[pz - 1][c] = acc;
    __syncthreads();
    if (pz == 0) {
        float tot = acc + part[0][c] + part[1][c] + part[2][c];
        if (q < ED) g_M[q * SD + c] = __uint_as_float(f2tf32(tot));
        else        g_c0[c] = b0[c] + tot;
    }
}

// ---- K3a: per-mol mean ----
__global__ void k_molmean(const int* __restrict__ batch) {
    __shared__ float red[128][4];
    const int b = blockIdx.x;
    const int t = threadIdx.x;
    float sx = 0.f, sy = 0.f, sz = 0.f, c = 0.f;
    for (int n = t; n < NN; n += 128) {
        if (batch[n] == b) {
            sx += g_cpraw[n * 3 + 0];
            sy += g_cpraw[n * 3 + 1];
            sz += g_cpraw[n * 3 + 2];
            c  += 1.0f;
        }
    }
    red[t][0] = sx; red[t][1] = sy; red[t][2] = sz; red[t][3] = c;
    __syncthreads();
    for (int s = 64; s > 0; s >>= 1) {
        if (t < s) {
            red[t][0] += red[t + s][0];
            red[t][1] += red[t + s][1];
            red[t][2] += red[t + s][2];
            red[t][3] += red[t + s][3];
        }
        __syncthreads();
    }
    if (t < 3) g_molmean[b * 3 + t] = red[0][t] / fmaxf(red[0][3], 1.0f);
}

// ---- K3b: center coords + write output ----
__global__ void k_center(const int* __restrict__ batch, float* __restrict__ out_coords) {
    int n = blockIdx.x * blockDim.x + threadIdx.x;
    if (n < NN) {
        int b = batch[n];
        #pragma unroll
        for (int x = 0; x < 3; x++) {
            float cpv = g_cpraw[n * 3 + x] - g_molmean[b * 3 + x];
            g_cp[n * 3 + x] = cpv;
            out_coords[n * 3 + x] = cpv;
        }
    }
}

// ---- K6: mma.sync tf32 edge kernel. 64 edges/CTA, 8 warps. (unchanged) ----
#define BPAD 264
#define APAD 36
#define SM_B    0
#define SM_A    33792
#define SM_W1   43008
#define SM_C0   51200
#define SM_WD   52224
#define SM_DD   53248
#define SM_II   53504
#define SM_JJ   53760
#define SM_KA   54016
#define SM_KB   54272
#define SM_TOTAL 54528

__global__ __launch_bounds__(256, 2) void k_edge(
    const int* __restrict__ eg, const float* __restrict__ efeat,
    const float* __restrict__ W0, const float* __restrict__ W1,
    const float* __restrict__ b1, float* __restrict__ out_bonds)
{
    extern __shared__ char smem[];
    uint32_t* sB  = (uint32_t*)(smem + SM_B);
    uint32_t* sA  = (uint32_t*)(smem + SM_A);
    float*    sW1 = (float*)(smem + SM_W1);
    float*    sC0 = (float*)(smem + SM_C0);
    float*    sWD = (float*)(smem + SM_WD);
    float*    sDD = (float*)(smem + SM_DD);
    int*      sII = (int*)  (smem + SM_II);
    int*      sJJ = (int*)  (smem + SM_JJ);
    int*      sKA = (int*)  (smem + SM_KA);
    int*      sKB = (int*)  (smem + SM_KB);

    const int t    = threadIdx.x;
    const int lane = t & 31;
    const int wid  = t >> 5;
    const int base = blockIdx.x * EPC;

    {   // stage B [32][256] (tf32 bits) into padded smem
        const float4* src = (const float4*)g_M;
        #pragma unroll
        for (int r = 0; r < 8; r++) {
            int idx = t + 256 * r;
            int k = idx >> 6, n4 = idx & 63;
            *(float4*)&sB[k * BPAD + n4 * 4] = src[idx];
        }
    }
    {   // stage W1 (scalar — rows only 4B-aligned), c0, wd
        sW1[t * 8 + 0] = W1[t * NBT + 0];
        sW1[t * 8 + 1] = W1[t * NBT + 1];
        sW1[t * 8 + 2] = W1[t * NBT + 2];
        sW1[t * 8 + 3] = W1[t * NBT + 3];
        sW1[t * 8 + 4] = W1[t * NBT + 4];
        sC0[t] = g_c0[t];
        sWD[t] = W0[(size_t)SD * SD + t];
    }
    if (t < EPC) {
        int eid = base + t;
        int j = eg[eid], i = eg[EE + eid];
        sII[t] = i; sJJ[t] = j;
        sKA[t] = g_map[j * NN + i];
        sKB[t] = g_map[i * NN + j];
        float dx = g_cp[i * 3 + 0] - g_cp[j * 3 + 0];
        float dy = g_cp[i * 3 + 1] - g_cp[j * 3 + 1];
        float dz = g_cp[i * 3 + 2] - g_cp[j * 3 + 2];
        sDD[t] = dx * dx + dy * dy + dz * dz;
    }
    __syncthreads();

    {   // build A = e_sym [64][32] tf32
        int m = t >> 2;
        int qd = t & 3;
        int ka = sKA[m], kb = sKB[m];
        const float4* ea = (const float4*)&efeat[ka * ED + qd * 8];
        float4 v0 = ea[0], v1 = ea[1];
        if (kb >= 0) {
            const float4* ebp = (const float4*)&efeat[kb * ED + qd * 8];
            float4 w0 = ebp[0], w1 = ebp[1];
            v0.x += w0.x; v0.y += w0.y; v0.z += w0.z; v0.w += w0.w;
            v1.x += w1.x; v1.y += w1.y; v1.z += w1.z; v1.w += w1.w;
        }
        uint32_t* dst = &sA[m * APAD + qd * 8];
        dst[0] = f2tf32(0.5f * v0.x); dst[1] = f2tf32(0.5f * v0.y);
        dst[2] = f2tf32(0.5f * v0.z); dst[3] = f2tf32(0.5f * v0.w);
        dst[4] = f2tf32(0.5f * v1.x); dst[5] = f2tf32(0.5f * v1.y);
        dst[6] = f2tf32(0.5f * v1.z); dst[7] = f2tf32(0.5f * v1.w);
    }
    __syncthreads();

    const int g  = lane >> 2;
    const int tg = lane & 3;
    const int wm = wid >> 2;
    const int wn = wid & 3;

    float acc[2][8][4];
    #pragma unroll
    for (int mf = 0; mf < 2; mf++)
        #pragma unroll
        for (int nf = 0; nf < 8; nf++)
            #pragma unroll
            for (int x = 0; x < 4; x++) acc[mf][nf][x] = 0.0f;

    #pragma unroll
    for (int ks = 0; ks < 4; ks++) {
        uint32_t a[2][4];
        #pragma unroll
        for (int mf = 0; mf < 2; mf++) {
            int r0 = wm * 32 + mf * 16 + g;
            a[mf][0] = sA[(r0 + 0) * APAD + ks * 8 + tg];
            a[mf][1] = sA[(r0 + 8) * APAD + ks * 8 + tg];
            a[mf][2] = sA[(r0 + 0) * APAD + ks * 8 + tg + 4];
            a[mf][3] = sA[(r0 + 8) * APAD + ks * 8 + tg + 4];
        }
        #pragma unroll
        for (int nf = 0; nf < 8; nf++) {
            int cc = wn * 64 + nf * 8 + g;
            uint32_t b0 = sB[(ks * 8 + tg + 0) * BPAD + cc];
            uint32_t b1 = sB[(ks * 8 + tg + 4) * BPAD + cc];
            mma_tf32(acc[0][nf], a[0], b0, b1);
            mma_tf32(acc[1][nf], a[1], b0, b1);
        }
    }

    float pb[4][NBT];
    #pragma unroll
    for (int r = 0; r < 4; r++)
        #pragma unroll
        for (int b = 0; b < NBT; b++) pb[r][b] = 0.0f;

    #pragma unroll
    for (int mf = 0; mf < 2; mf++) {
        #pragma unroll
        for (int h = 0; h < 2; h++) {
            int m = wm * 32 + mf * 16 + g + h * 8;
            const float* Gi = &g_G[sII[m] * SD];
            const float* Gj = &g_G[sJJ[m] * SD];
            float dm = sDD[m];
            int r = mf * 2 + h;
            #pragma unroll
            for (int nf = 0; nf < 8; nf++) {
                int col = wn * 64 + nf * 8 + 2 * tg;
                float2 gi = *(const float2*)&Gi[col];
                float2 gj = *(const float2*)&Gj[col];
                float z0 = acc[mf][nf][h * 2 + 0] + sC0[col + 0]
                         + gi.x + gj.x + dm * sWD[col + 0];
                float z1 = acc[mf][nf][h * 2 + 1] + sC0[col + 1]
                         + gi.y + gj.y + dm * sWD[col + 1];
                float h0 = silu_f(z0);
                float h1 = silu_f(z1);
                float4 wa = *(const float4*)&sW1[(col + 0) * 8];
                float  wae = sW1[(col + 0) * 8 + 4];
                float4 wb = *(const float4*)&sW1[(col + 1) * 8];
                float  wbe = sW1[(col + 1) * 8 + 4];
                pb[r][0] += h0 * wa.x + h1 * wb.x;
                pb[r][1] += h0 * wa.y + h1 * wb.y;
                pb[r][2] += h0 * wa.z + h1 * wb.z;
                pb[r][3] += h0 * wa.w + h1 * wb.w;
                pb[r][4] += h0 * wae  + h1 * wbe;
            }
        }
    }

    #pragma unroll
    for (int off = 2; off >= 1; off >>= 1)
        #pragma unroll
        for (int r = 0; r < 4; r++)
            #pragma unroll
            for (int b = 0; b < NBT; b++)
                pb[r][b] += __shfl_down_sync(0xffffffffu, pb[r][b], off, 4);

    __shared__ float sRed[4][EPC][NBT + 1];
    if (tg == 0) {
        #pragma unroll
        for (int r = 0; r < 4; r++) {
            int m = wm * 32 + (r >> 1) * 16 + g + (r & 1) * 8;
            #pragma unroll
            for (int b = 0; b < NBT; b++) sRed[wn][m][b] = pb[r][b];
        }
    }
    __syncthreads();
    for (int idx = t; idx < EPC * NBT; idx += 256) {
        int m = idx / NBT, b = idx % NBT;
        float sum = sRed[0][m][b] + sRed[1][m][b] + sRed[2][m][b] + sRed[3][m][b];
        out_bonds[(base + m) * NBT + b] = sum + __ldg(&b1[b]);
    }
}

extern "C" void kernel_launch(void* const* d_in, const int* in_sizes, int n_in,
                              void* d_out, int out_size)
{
    const float* s     = (const float*)d_in[0];
    const float* v     = (const float*)d_in[1];
    const float* p     = (const float*)d_in[2];
    const float* e     = (const float*)d_in[3];
    const int*   batch = (const int*)  d_in[4];
    const int*   eg    = (const int*)  d_in[5];
    const float* Ws    = (const float*)d_in[6];
    const float* bs    = (const float*)d_in[7];
    const float* Wc    = (const float*)d_in[8];
    const float* Wa    = (const float*)d_in[9];
    const float* ba    = (const float*)d_in[10];
    const float* Wb    = (const float*)d_in[11];
    const float* bb    = (const float*)d_in[12];
    const float* W0    = (const float*)d_in[13];
    const float* b0    = (const float*)d_in[14];
    const float* W1    = (const float*)d_in[15];
    const float* b1    = (const float*)d_in[16];

    float* out        = (float*)d_out;
    float* out_coords = out;                         // [2048, 3]
    float* out_atoms  = out + NN * 3;                // [2048, 16]
    float* out_bonds  = out + NN * 3 + NN * NAF;     // [262144, 5]

    cudaFuncSetAttribute(k_edge, cudaFuncAttributeMaxDynamicSharedMemorySize, SM_TOTAL);

    // fork-join: side stream runs map + constant prep concurrently with node prep
    cudaStream_t s1;
    cudaEvent_t evFork, evJoin;
    cudaStreamCreateWithFlags(&s1, cudaStreamNonBlocking);
    cudaEventCreateWithFlags(&evFork, cudaEventDisableTiming);
    cudaEventCreateWithFlags(&evJoin, cudaEventDisableTiming);

    cudaEventRecord(evFork, 0);
    cudaStreamWaitEvent(s1, evFork, 0);

    // side stream: independent of node features
    k_clear  <<<2048, 256, 0, s1>>>();
    k_scatter<<<EE / 256, 256, 0, s1>>>(eg);
    k_mw     <<<ED + 1, 1024, 0, s1>>>(Wb, bb, W0, b0);

    // main stream: node-feature chain
    k_node   <<<NN / 16, 256>>>(s, v, p, Ws, bs, Wc, W0, Wa, ba, out_atoms);
    k_molmean<<<NMOL, 128>>>(batch);
    k_center <<<NN / 256, 256>>>(batch, out_coords);

    cudaEventRecord(evJoin, s1);
    cudaStreamWaitEvent(0, evJoin, 0);

    k_edge   <<<EE / EPC, 256, SM_TOTAL>>>(eg, e, W0, W1, b1, out_bonds);
    // streams/events intentionally not destroyed: kernel_launch is called only
    // for the eager correctness run and once under graph capture; destroying a
    // stream that participated in an active capture invalidates the capture.
}

// round 13
// speedup vs baseline: 1.0487x; 1.0487x over previous
#include <cuda_runtime.h>
#include <cstdint>

#define NN   2048
#define EE   262144
#define SD   256
#define VD   64
#define ED   32
#define NMOL 64
#define NAF  16
#define NBT  5
#define EPC  64            // edges per CTA in k_edge
#define NPC  32            // nodes per CTA in k_node
#define NROW 264           // padded row stride (floats) in k_node smem

// ---- scratch (device globals; no allocations) ----
__device__ __align__(16) float g_G[NN * SD];         // G = s_h @ W0[0:256,:] (fp32 accum)
__device__ __align__(16) float g_cpraw[NN * 3];
__device__ __align__(16) float g_cp[NN * 3];
__device__ __align__(16) float g_molmean[NMOL * 3];
__device__ __align__(16) float g_M[ED * SD];         // M = Wb@W0a, tf32-rounded bits
__device__ __align__(16) float g_c0[SD];             // c0 = b0 + bb @ W0a (fp32)
__device__ int   g_map[NN * NN];

__device__ __forceinline__ float silu_f(float x) {
    return __fdividef(x, 1.0f + __expf(-x));
}

__device__ __forceinline__ uint32_t f2tf32(float x) {
    uint32_t r;
    asm("cvt.rna.tf32.f32 %0, %1;" : "=r"(r) : "f"(x));
    return r;
}

// m16n8k8 tf32 mma: D += A@B  (A row-major, B col-major)
__device__ __forceinline__ void mma_tf32(float* c, const uint32_t* a,
                                         uint32_t b0, uint32_t b1) {
    asm volatile(
        "mma.sync.aligned.m16n8k8.row.col.f32.tf32.tf32.f32 "
        "{%0,%1,%2,%3}, {%4,%5,%6,%7}, {%8,%9}, {%0,%1,%2,%3};\n"
        : "+f"(c[0]), "+f"(c[1]), "+f"(c[2]), "+f"(c[3])
        : "r"(a[0]), "r"(a[1]), "r"(a[2]), "r"(a[3]), "r"(b0), "r"(b1));
}

// ---- K0: clear map ----
__global__ void k_clear() {
    int i = blockIdx.x * blockDim.x + threadIdx.x;
    int stride = gridDim.x * blockDim.x;
    for (; i < NN * NN; i += stride) g_map[i] = -1;
}

// ---- K5: scatter last-edge-wins ----
__global__ void k_scatter(const int* __restrict__ eg) {
    int k = blockIdx.x * blockDim.x + threadIdx.x;
    if (k < EE) {
        int j = eg[k];
        int i = eg[EE + k];
        atomicMax(&g_map[j * NN + i], k);
    }
}

// ---- K1: tensor-core node kernel: 32 nodes/CTA ----
// GEMM1: z1 = s@Ws (tf32 mma) ; s_h = silu(z1+bs) kept fp32 in smem
// GEMM2: G = s_h@W0[0:256,:] (tf32 mma) -> g_G
// atoms = s_h@Wa + ba (FFMA from smem) ; coords = p + v@Wc
#define NSM_S 0                        // sS [32][264] f32
#define NSM_W (NPC * NROW)             // sW [32][264] u32/f32 (B chunk / Wa)
#define NSM_H (2 * NPC * NROW)         // sH [32][264] f32
#define NSM_TOTAL (3 * NPC * NROW * 4)

__global__ __launch_bounds__(256) void k_node(
    const float* __restrict__ s, const float* __restrict__ v,
    const float* __restrict__ p, const float* __restrict__ Ws,
    const float* __restrict__ bs, const float* __restrict__ Wc,
    const float* __restrict__ W0, const float* __restrict__ Wa,
    const float* __restrict__ ba, float* __restrict__ out_atoms)
{
    extern __shared__ float nsm[];
    float*    sS = nsm + NSM_S;
    uint32_t* sW = (uint32_t*)(nsm + NSM_W);
    float*    sH = nsm + NSM_H;

    const int t    = threadIdx.x;
    const int lane = t & 31;
    const int wid  = t >> 5;
    const int n0   = blockIdx.x * NPC;
    const int g    = lane >> 2;        // 0..7
    const int tg   = lane & 3;         // 0..3
    const int cb   = wid * 32;         // this warp's 32-col band

    // ---- stage sS = s[n0..n0+31][0..255] (2048 float4) ----
    {
        const float4* src = (const float4*)s;
        #pragma unroll
        for (int r8 = 0; r8 < 8; r8++) {
            int idx = t + 256 * r8;
            int row = idx >> 6, c4 = idx & 63;
            *(float4*)&sS[row * NROW + c4 * 4] = src[(n0 + row) * 64 + c4];
        }
    }
    // coords = p + v@Wc  (32 nodes x 3 axes)
    if (t < NPC * 3) {
        int r = t / 3, x = t % 3;
        const float* vp = &v[(n0 + r) * 3 * VD + x * VD];
        float sum = 0.0f;
        #pragma unroll 8
        for (int q = 0; q < VD; q++) sum += vp[q] * Wc[q];
        g_cpraw[(n0 + r) * 3 + x] = p[(n0 + r) * 3 + x] + sum;
    }

    float acc[2][4][4];

    // ================= GEMM1: s @ Ws =================
    #pragma unroll
    for (int mf = 0; mf < 2; mf++)
        #pragma unroll
        for (int nf = 0; nf < 4; nf++)
            #pragma unroll
            for (int x = 0; x < 4; x++) acc[mf][nf][x] = 0.0f;

    for (int kc = 0; kc < 8; kc++) {
        {   // stage Ws rows kc*32..+31 (tf32-converted)
            const float4* src = (const float4*)Ws;
            #pragma unroll
            for (int r8 = 0; r8 < 8; r8++) {
                int idx = t + 256 * r8;
                int row = idx >> 6, c4 = idx & 63;
                float4 w = src[(kc * 32 + row) * 64 + c4];
                uint32_t* dst = &sW[row * NROW + c4 * 4];
                dst[0] = f2tf32(w.x); dst[1] = f2tf32(w.y);
                dst[2] = f2tf32(w.z); dst[3] = f2tf32(w.w);
            }
        }
        __syncthreads();
        #pragma unroll
        for (int ks = 0; ks < 4; ks++) {
            uint32_t a[2][4];
            #pragma unroll
            for (int mf = 0; mf < 2; mf++) {
                int r0 = mf * 16 + g;
                int kk = kc * 32 + ks * 8 + tg;
                a[mf][0] = f2tf32(sS[(r0 + 0) * NROW + kk]);
                a[mf][1] = f2tf32(sS[(r0 + 8) * NROW + kk]);
                a[mf][2] = f2tf32(sS[(r0 + 0) * NROW + kk + 4]);
                a[mf][3] = f2tf32(sS[(r0 + 8) * NROW + kk + 4]);
            }
            #pragma unroll
            for (int nf = 0; nf < 4; nf++) {
                int cc = cb + nf * 8 + g;
                uint32_t b0 = sW[(ks * 8 + tg + 0) * NROW + cc];
                uint32_t b1 = sW[(ks * 8 + tg + 4) * NROW + cc];
                mma_tf32(acc[0][nf], a[0], b0, b1);
                mma_tf32(acc[1][nf], a[1], b0, b1);
            }
        }
        __syncthreads();
    }

    // bias + silu -> sH (fp32)
    #pragma unroll
    for (int mf = 0; mf < 2; mf++)
        #pragma unroll
        for (int nf = 0; nf < 4; nf++)
            #pragma unroll
            for (int h = 0; h < 2; h++)
                #pragma unroll
                for (int x = 0; x < 2; x++) {
                    int row = mf * 16 + g + h * 8;
                    int col = cb + nf * 8 + 2 * tg + x;
                    float z = acc[mf][nf][h * 2 + x] + __ldg(&bs[col]);
                    sH[row * NROW + col] = silu_f(z);
                }
    __syncthreads();

    // ================= GEMM2: s_h @ W0a =================
    #pragma unroll
    for (int mf = 0; mf < 2; mf++)
        #pragma unroll
        for (int nf = 0; nf < 4; nf++)
            #pragma unroll
            for (int x = 0; x < 4; x++) acc[mf][nf][x] = 0.0f;

    for (int kc = 0; kc < 8; kc++) {
        {   // stage W0 rows kc*32..+31 (tf32-converted)
            const float4* src = (const float4*)W0;
            #pragma unroll
            for (int r8 = 0; r8 < 8; r8++) {
                int idx = t + 256 * r8;
                int row = idx >> 6, c4 = idx & 63;
                float4 w = src[(kc * 32 + row) * 64 + c4];
                uint32_t* dst = &sW[row * NROW + c4 * 4];
                dst[0] = f2tf32(w.x); dst[1] = f2tf32(w.y);
                dst[2] = f2tf32(w.z); dst[3] = f2tf32(w.w);
            }
        }
        __syncthreads();
        #pragma unroll
        for (int ks = 0; ks < 4; ks++) {
            uint32_t a[2][4];
            #pragma unroll
            for (int mf = 0; mf < 2; mf++) {
                int r0 = mf * 16 + g;
                int kk = kc * 32 + ks * 8 + tg;
                a[mf][0] = f2tf32(sH[(r0 + 0) * NROW + kk]);
                a[mf][1] = f2tf32(sH[(r0 + 8) * NROW + kk]);
                a[mf][2] = f2tf32(sH[(r0 + 0) * NROW + kk + 4]);
                a[mf][3] = f2tf32(sH[(r0 + 8) * NROW + kk + 4]);
            }
            #pragma unroll
            for (int nf = 0; nf < 4; nf++) {
                int cc = cb + nf * 8 + g;
                uint32_t b0 = sW[(ks * 8 + tg + 0) * NROW + cc];
                uint32_t b1 = sW[(ks * 8 + tg + 4) * NROW + cc];
                mma_tf32(acc[0][nf], a[0], b0, b1);
                mma_tf32(acc[1][nf], a[1], b0, b1);
            }
        }
        __syncthreads();
    }

    // write G fragments (float2: cols 2tg,2tg+1)
    #pragma unroll
    for (int mf = 0; mf < 2; mf++)
        #pragma unroll
        for (int nf = 0; nf < 4; nf++)
            #pragma unroll
            for (int h = 0; h < 2; h++) {
                int row = mf * 16 + g + h * 8;
                int col = cb + nf * 8 + 2 * tg;
                float2 val = make_float2(acc[mf][nf][h * 2 + 0],
                                         acc[mf][nf][h * 2 + 1]);
                *(float2*)&g_G[(n0 + row) * SD + col] = val;
            }

    // ---- atoms = s_h @ Wa + ba: stage Wa into sW (as f32), then FFMA ----
    {
        float* sWa = (float*)sW;
        const float4* src = (const float4*)Wa;     // [256*16] floats = 1024 f4
        #pragma unroll
        for (int r4 = 0; r4 < 4; r4++) {
            int idx = t + 256 * r4;
            *(float4*)&sWa[idx * 4] = src[idx];
        }
    }
    __syncthreads();
    {
        float* sWa = (float*)sW;
        int af = t & 15;
        int nd = t >> 4;                           // 0..15; handles nd and nd+16
        float s0 = 0.0f, s1 = 0.0f;
        const float* h0 = &sH[nd * NROW];
        const float* h1 = &sH[(nd + 16) * NROW];
        for (int k = 0; k < SD; k += 4) {
            float4 a0 = *(const float4*)&h0[k];
            float4 a1 = *(const float4*)&h1[k];
            float w0 = sWa[(k + 0) * NAF + af];
            float w1 = sWa[(k + 1) * NAF + af];
            float w2 = sWa[(k + 2) * NAF + af];
            float w3 = sWa[(k + 3) * NAF + af];
            s0 += a0.x * w0 + a0.y * w1 + a0.z * w2 + a0.w * w3;
            s1 += a1.x * w0 + a1.y * w1 + a1.z * w2 + a1.w * w3;
        }
        float bav = __ldg(&ba[af]);
        out_atoms[(n0 + nd) * NAF + af]      = s0 + bav;
        out_atoms[(n0 + nd + 16) * NAF + af] = s1 + bav;
    }
}

// ---- K2: g_M[k][n] = (Wb@W0a)[k][n] tf32-rounded; c0 = b0 + bb@W0a ----
__global__ __launch_bounds__(1024) void k_mw(
    const float* __restrict__ Wb, const float* __restrict__ bb,
    const float* __restrict__ W0, const float* __restrict__ b0)
{
    __shared__ float row[SD];
    __shared__ float part[3][SD];
    const int t = threadIdx.x;
    const int c = t & 255;
    const int pz = t >> 8;
    const int q = blockIdx.x;
    if (t < SD) row[t] = (q < ED) ? Wb[q * SD + t] : bb[t];
    __syncthreads();

    float acc = 0.0f;
    const int k0 = pz * 64;
    #pragma unroll 4
    for (int k = k0; k < k0 + 64; k += 4) {
        float4 a = *(const float4*)&row[k];
        acc += a.x * W0[(k + 0) * SD + c];
        acc += a.y * W0[(k + 1) * SD + c];
        acc += a.z * W0[(k + 2) * SD + c];
        acc += a.w * W0[(k + 3) * SD + c];
    }
    if (pz > 0) part[pz - 1][c] = acc;
    __syncthreads();
    if (pz == 0) {
        float tot = acc + part[0][c] + part[1][c] + part[2][c];
        if (q < ED) g_M[q * SD + c] = __uint_as_float(f2tf32(tot));
        else        g_c0[c] = b0[c] + tot;
    }
}

// ---- K3a: per-mol mean ----
__global__ void k_molmean(const int* __restrict__ batch) {
    __shared__ float red[128][4];
    const int b = blockIdx.x;
    const int t = threadIdx.x;
    float sx = 0.f, sy = 0.f, sz = 0.f, c = 0.f;
    for (int n = t; n < NN; n += 128) {
        if (batch[n] == b) {
            sx += g_cpraw[n * 3 + 0];
            sy += g_cpraw[n * 3 + 1];
            sz += g_cpraw[n * 3 + 2];
            c  += 1.0f;
        }
    }
    red[t][0] = sx; red[t][1] = sy; red[t][2] = sz; red[t][3] = c;
    __syncthreads();
    for (int s = 64; s > 0; s >>= 1) {
        if (t < s) {
            red[t][0] += red[t + s][0];
            red[t][1] += red[t + s][1];
            red[t][2] += red[t + s][2];
            red[t][3] += red[t + s][3];
        }
        __syncthreads();
    }
    if (t < 3) g_molmean[b * 3 + t] = red[0][t] / fmaxf(red[0][3], 1.0f);
}

// ---- K3b: center coords + write output ----
__global__ void k_center(const int* __restrict__ batch, float* __restrict__ out_coords) {
    int n = blockIdx.x * blockDim.x + threadIdx.x;
    if (n < NN) {
        int b = batch[n];
        #pragma unroll
        for (int x = 0; x < 3; x++) {
            float cpv = g_cpraw[n * 3 + x] - g_molmean[b * 3 + x];
            g_cp[n * 3 + x] = cpv;
            out_coords[n * 3 + x] = cpv;
        }
    }
}

// ---- K6: mma.sync tf32 edge kernel. 64 edges/CTA, 8 warps. (unchanged) ----
#define BPAD 264
#define APAD 36
#define SM_B    0
#define SM_A    33792
#define SM_W1   43008
#define SM_C0   51200
#define SM_WD   52224
#define SM_DD   53248
#define SM_II   53504
#define SM_JJ   53760
#define SM_KA   54016
#define SM_KB   54272
#define SM_TOTAL 54528

__global__ __launch_bounds__(256, 2) void k_edge(
    const int* __restrict__ eg, const float* __restrict__ efeat,
    const float* __restrict__ W0, const float* __restrict__ W1,
    const float* __restrict__ b1, float* __restrict__ out_bonds)
{
    extern __shared__ char smem[];
    uint32_t* sB  = (uint32_t*)(smem + SM_B);
    uint32_t* sA  = (uint32_t*)(smem + SM_A);
    float*    sW1 = (float*)(smem + SM_W1);
    float*    sC0 = (float*)(smem + SM_C0);
    float*    sWD = (float*)(smem + SM_WD);
    float*    sDD = (float*)(smem + SM_DD);
    int*      sII = (int*)  (smem + SM_II);
    int*      sJJ = (int*)  (smem + SM_JJ);
    int*      sKA = (int*)  (smem + SM_KA);
    int*      sKB = (int*)  (smem + SM_KB);

    const int t    = threadIdx.x;
    const int lane = t & 31;
    const int wid  = t >> 5;
    const int base = blockIdx.x * EPC;

    {
        const float4* src = (const float4*)g_M;
        #pragma unroll
        for (int r = 0; r < 8; r++) {
            int idx = t + 256 * r;
            int k = idx >> 6, n4 = idx & 63;
            *(float4*)&sB[k * BPAD + n4 * 4] = src[idx];
        }
    }
    {
        sW1[t * 8 + 0] = W1[t * NBT + 0];
        sW1[t * 8 + 1] = W1[t * NBT + 1];
        sW1[t * 8 + 2] = W1[t * NBT + 2];
        sW1[t * 8 + 3] = W1[t * NBT + 3];
        sW1[t * 8 + 4] = W1[t * NBT + 4];
        sC0[t] = g_c0[t];
        sWD[t] = W0[(size_t)SD * SD + t];
    }
    if (t < EPC) {
        int eid = base + t;
        int j = eg[eid], i = eg[EE + eid];
        sII[t] = i; sJJ[t] = j;
        sKA[t] = g_map[j * NN + i];
        sKB[t] = g_map[i * NN + j];
        float dx = g_cp[i * 3 + 0] - g_cp[j * 3 + 0];
        float dy = g_cp[i * 3 + 1] - g_cp[j * 3 + 1];
        float dz = g_cp[i * 3 + 2] - g_cp[j * 3 + 2];
        sDD[t] = dx * dx + dy * dy + dz * dz;
    }
    __syncthreads();

    {
        int m = t >> 2;
        int qd = t & 3;
        int ka = sKA[m], kb = sKB[m];
        const float4* ea = (const float4*)&efeat[ka * ED + qd * 8];
        float4 v0 = ea[0], v1 = ea[1];
        if (kb >= 0) {
            const float4* ebp = (const float4*)&efeat[kb * ED + qd * 8];
            float4 w0 = ebp[0], w1 = ebp[1];
            v0.x += w0.x; v0.y += w0.y; v0.z += w0.z; v0.w += w0.w;
            v1.x += w1.x; v1.y += w1.y; v1.z += w1.z; v1.w += w1.w;
        }
        uint32_t* dst = &sA[m * APAD + qd * 8];
        dst[0] = f2tf32(0.5f * v0.x); dst[1] = f2tf32(0.5f * v0.y);
        dst[2] = f2tf32(0.5f * v0.z); dst[3] = f2tf32(0.5f * v0.w);
        dst[4] = f2tf32(0.5f * v1.x); dst[5] = f2tf32(0.5f * v1.y);
        dst[6] = f2tf32(0.5f * v1.z); dst[7] = f2tf32(0.5f * v1.w);
    }
    __syncthreads();

    const int g  = lane >> 2;
    const int tg = lane & 3;
    const int wm = wid >> 2;
    const int wn = wid & 3;

    float acc[2][8][4];
    #pragma unroll
    for (int mf = 0; mf < 2; mf++)
        #pragma unroll
        for (int nf = 0; nf < 8; nf++)
            #pragma unroll
            for (int x = 0; x < 4; x++) acc[mf][nf][x] = 0.0f;

    #pragma unroll
    for (int ks = 0; ks < 4; ks++) {
        uint32_t a[2][4];
        #pragma unroll
        for (int mf = 0; mf < 2; mf++) {
            int r0 = wm * 32 + mf * 16 + g;
            a[mf][0] = sA[(r0 + 0) * APAD + ks * 8 + tg];
            a[mf][1] = sA[(r0 + 8) * APAD + ks * 8 + tg];
            a[mf][2] = sA[(r0 + 0) * APAD + ks * 8 + tg + 4];
            a[mf][3] = sA[(r0 + 8) * APAD + ks * 8 + tg + 4];
        }
        #pragma unroll
        for (int nf = 0; nf < 8; nf++) {
            int cc = wn * 64 + nf * 8 + g;
            uint32_t b0 = sB[(ks * 8 + tg + 0) * BPAD + cc];
            uint32_t b1 = sB[(ks * 8 + tg + 4) * BPAD + cc];
            mma_tf32(acc[0][nf], a[0], b0, b1);
            mma_tf32(acc[1][nf], a[1], b0, b1);
        }
    }

    float pb[4][NBT];
    #pragma unroll
    for (int r = 0; r < 4; r++)
        #pragma unroll
        for (int b = 0; b < NBT; b++) pb[r][b] = 0.0f;

    #pragma unroll
    for (int mf = 0; mf < 2; mf++) {
        #pragma unroll
        for (int h = 0; h < 2; h++) {
            int m = wm * 32 + mf * 16 + g + h * 8;
            const float* Gi = &g_G[sII[m] * SD];
            const float* Gj = &g_G[sJJ[m] * SD];
            float dm = sDD[m];
            int r = mf * 2 + h;
            #pragma unroll
            for (int nf = 0; nf < 8; nf++) {
                int col = wn * 64 + nf * 8 + 2 * tg;
                float2 gi = *(const float2*)&Gi[col];
                float2 gj = *(const float2*)&Gj[col];
                float z0 = acc[mf][nf][h * 2 + 0] + sC0[col + 0]
                         + gi.x + gj.x + dm * sWD[col + 0];
                float z1 = acc[mf][nf][h * 2 + 1] + sC0[col + 1]
                         + gi.y + gj.y + dm * sWD[col + 1];
                float h0 = silu_f(z0);
                float h1 = silu_f(z1);
                float4 wa = *(const float4*)&sW1[(col + 0) * 8];
                float  wae = sW1[(col + 0) * 8 + 4];
                float4 wb = *(const float4*)&sW1[(col + 1) * 8];
                float  wbe = sW1[(col + 1) * 8 + 4];
                pb[r][0] += h0 * wa.x + h1 * wb.x;
                pb[r][1] += h0 * wa.y + h1 * wb.y;
                pb[r][2] += h0 * wa.z + h1 * wb.z;
                pb[r][3] += h0 * wa.w + h1 * wb.w;
                pb[r][4] += h0 * wae  + h1 * wbe;
            }
        }
    }

    #pragma unroll
    for (int off = 2; off >= 1; off >>= 1)
        #pragma unroll
        for (int r = 0; r < 4; r++)
            #pragma unroll
            for (int b = 0; b < NBT; b++)
                pb[r][b] += __shfl_down_sync(0xffffffffu, pb[r][b], off, 4);

    __shared__ float sRed[4][EPC][NBT + 1];
    if (tg == 0) {
        #pragma unroll
        for (int r = 0; r < 4; r++) {
            int m = wm * 32 + (r >> 1) * 16 + g + (r & 1) * 8;
            #pragma unroll
            for (int b = 0; b < NBT; b++) sRed[wn][m][b] = pb[r][b];
        }
    }
    __syncthreads();
    for (int idx = t; idx < EPC * NBT; idx += 256) {
        int m = idx / NBT, b = idx % NBT;
        float sum = sRed[0][m][b] + sRed[1][m][b] + sRed[2][m][b] + sRed[3][m][b];
        out_bonds[(base + m) * NBT + b] = sum + __ldg(&b1[b]);
    }
}

extern "C" void kernel_launch(void* const* d_in, const int* in_sizes, int n_in,
                              void* d_out, int out_size)
{
    const float* s     = (const float*)d_in[0];
    const float* v     = (const float*)d_in[1];
    const float* p     = (const float*)d_in[2];
    const float* e     = (const float*)d_in[3];
    const int*   batch = (const int*)  d_in[4];
    const int*   eg    = (const int*)  d_in[5];
    const float* Ws    = (const float*)d_in[6];
    const float* bs    = (const float*)d_in[7];
    const float* Wc    = (const float*)d_in[8];
    const float* Wa    = (const float*)d_in[9];
    const float* ba    = (const float*)d_in[10];
    const float* Wb    = (const float*)d_in[11];
    const float* bb    = (const float*)d_in[12];
    const float* W0    = (const float*)d_in[13];
    const float* b0    = (const float*)d_in[14];
    const float* W1    = (const float*)d_in[15];
    const float* b1    = (const float*)d_in[16];

    float* out        = (float*)d_out;
    float* out_coords = out;                         // [2048, 3]
    float* out_atoms  = out + NN * 3;                // [2048, 16]
    float* out_bonds  = out + NN * 3 + NN * NAF;     // [262144, 5]

    cudaFuncSetAttribute(k_edge, cudaFuncAttributeMaxDynamicSharedMemorySize, SM_TOTAL);
    cudaFuncSetAttribute(k_node, cudaFuncAttributeMaxDynamicSharedMemorySize, NSM_TOTAL);

    // fork-join: side stream runs map + constant prep concurrently with node prep
    cudaStream_t s1;
    cudaEvent_t evFork, evJoin;
    cudaStreamCreateWithFlags(&s1, cudaStreamNonBlocking);
    cudaEventCreateWithFlags(&evFork, cudaEventDisableTiming);
    cudaEventCreateWithFlags(&evJoin, cudaEventDisableTiming);

    cudaEventRecord(evFork, 0);
    cudaStreamWaitEvent(s1, evFork, 0);

    // side stream: independent of node features
    k_clear  <<<2048, 256, 0, s1>>>();
    k_scatter<<<EE / 256, 256, 0, s1>>>(eg);
    k_mw     <<<ED + 1, 1024, 0, s1>>>(Wb, bb, W0, b0);

    // main stream: node-feature chain
    k_node   <<<NN / NPC, 256, NSM_TOTAL>>>(s, v, p, Ws, bs, Wc, W0, Wa, ba, out_atoms);
    k_molmean<<<NMOL, 128>>>(batch);
    k_center <<<NN / 256, 256>>>(batch, out_coords);

    cudaEventRecord(evJoin, s1);
    cudaStreamWaitEvent(0, evJoin, 0);

    k_edge   <<<EE / EPC, 256, SM_TOTAL>>>(eg, e, W0, W1, b1, out_bonds);
    // streams/events intentionally not destroyed: kernel_launch is called only
    // for the eager correctness run and once under graph capture; destroying a
    // stream that participated in an active capture invalidates the capture.
}